// round 9
// baseline (speedup 1.0000x reference)
#include <cuda_runtime.h>
#include <cuda_bf16.h>
#include <math.h>
#include <stdint.h>

// Problem constants (fixed by the dataset)
#define NN      20000
#define EE      320000
#define SED     768
#define HC1     512      // H1 * C1
#define H1      4
#define C1      128
#define FOUT    128
#define NEG     0.2f

// ---------------- device scratch (no allocation allowed) ----------------
__device__ float g_c1[HC1];                                 // sent @ W1[768:]
__device__ float g_h1pre[NN * HC1];                         // x @ W1a + c1 (f32)
__device__ float g_h1out[NN * HC1];                         // after GAT1 + bias + ELU (f32)
__device__ float g_h2pre[NN * FOUT];                        // h1out @ W2 (f32)
__device__ __align__(16) __nv_bfloat16 g_w1thi[HC1 * SED];  // W1a^T split hi  [512][768]
__device__ __align__(16) __nv_bfloat16 g_w1tlo[HC1 * SED];
__device__ __align__(16) __nv_bfloat16 g_w2thi[FOUT * HC1]; // W2^T split hi   [128][512]
__device__ __align__(16) __nv_bfloat16 g_w2tlo[FOUT * HC1];
__device__ __align__(8) float g_es1[NN * H1];
__device__ __align__(8) float g_ed1[NN * H1];
__device__ float g_es2[NN];
__device__ float g_ed2[NN];
__device__ int   g_deg[NN];
__device__ int   g_rowptr[NN + 1];
__device__ int   g_cur[NN];
__device__ int   g_ssrc[EE];                                // src node per dst-sorted edge slot
__device__ int   g_bsum[32];
__device__ int   g_boff[32];

// ---------------- zero ----------------
__global__ void k_zero() {
    int i = blockIdx.x * blockDim.x + threadIdx.x;
    if (i < NN) {
        g_deg[i] = 0;
        g_es2[i] = 0.f;
        g_ed2[i] = 0.f;
    }
    if (i < HC1) g_c1[i] = 0.f;
    if (i < NN * H1) { g_es1[i] = 0.f; g_ed1[i] = 0.f; }
}

// ---------------- CSR build (4 edges/thread for MLP) ----------------
__global__ void k_hist(const int* __restrict__ ei) {
    int base = (blockIdx.x * blockDim.x + threadIdx.x) * 4;
    if (base >= EE) return;
    int4 d = *reinterpret_cast<const int4*>(ei + EE + base);
    atomicAdd(&g_deg[d.x], 1);
    atomicAdd(&g_deg[d.y], 1);
    atomicAdd(&g_deg[d.z], 1);
    atomicAdd(&g_deg[d.w], 1);
}

#define SCAN_NB 20
__global__ void k_scanA() {
    __shared__ int wsum[32];
    const int t = threadIdx.x, lane = t & 31, wid = t >> 5;
    int i = blockIdx.x * 1024 + t;
    int v = (i < NN) ? g_deg[i] : 0;
    int incl = v;
#pragma unroll
    for (int o = 1; o < 32; o <<= 1) {
        int x = __shfl_up_sync(0xffffffffu, incl, o);
        if (lane >= o) incl += x;
    }
    if (lane == 31) wsum[wid] = incl;
    __syncthreads();
    if (wid == 0) {
        int s = wsum[lane];
#pragma unroll
        for (int o = 1; o < 32; o <<= 1) {
            int x = __shfl_up_sync(0xffffffffu, s, o);
            if (lane >= o) s += x;
        }
        wsum[lane] = s;
    }
    __syncthreads();
    int off = wid ? wsum[wid - 1] : 0;
    if (i < NN) g_rowptr[i] = off + incl - v;
    if (t == 1023) g_bsum[blockIdx.x] = off + incl;
}
__global__ void k_scanB() {
    int lane = threadIdx.x;
    int v = (lane < SCAN_NB) ? g_bsum[lane] : 0;
    int incl = v;
#pragma unroll
    for (int o = 1; o < 32; o <<= 1) {
        int x = __shfl_up_sync(0xffffffffu, incl, o);
        if (lane >= o) incl += x;
    }
    if (lane < SCAN_NB) g_boff[lane] = incl - v;
    if (lane == 31) g_rowptr[NN] = incl;
}
__global__ void k_scanC() {
    int i = blockIdx.x * 1024 + threadIdx.x;
    if (i < NN) {
        int r = g_rowptr[i] + g_boff[blockIdx.x];
        g_rowptr[i] = r;
        g_cur[i] = r;
    }
}

__global__ void k_scatter(const int* __restrict__ ei) {
    int base = (blockIdx.x * blockDim.x + threadIdx.x) * 4;
    if (base >= EE) return;
    int4 s = *reinterpret_cast<const int4*>(ei + base);
    int4 d = *reinterpret_cast<const int4*>(ei + EE + base);
    int p0 = atomicAdd(&g_cur[d.x], 1);
    int p1 = atomicAdd(&g_cur[d.y], 1);
    int p2 = atomicAdd(&g_cur[d.z], 1);
    int p3 = atomicAdd(&g_cur[d.w], 1);
    g_ssrc[p0] = s.x;
    g_ssrc[p1] = s.y;
    g_ssrc[p2] = s.z;
    g_ssrc[p3] = s.w;
}

// ---------------- c1 = sent @ W1[768:, :]  (48 blocks x 16 k-rows) ----------------
__global__ void k_c1(const float* __restrict__ sent, const float* __restrict__ W1) {
    const int b = blockIdx.x;
    const int t = threadIdx.x;
    const float* Wb = W1 + (size_t)(SED + b * 16) * HC1;
    float a0 = 0.f, a1 = 0.f;
#pragma unroll
    for (int k = 0; k < 16; ++k) {
        float s = sent[b * 16 + k];
        a0 += s * Wb[k * HC1 + t];
        a1 += s * Wb[k * HC1 + t + 256];
    }
    atomicAdd(&g_c1[t], a0);
    atomicAdd(&g_c1[t + 256], a1);
}

// ---------------- tiled transpose + split:  Out[n][k] = W[k][n] ----------------
__global__ void k_tsplit(const float* __restrict__ W, __nv_bfloat16* __restrict__ Oh,
                         __nv_bfloat16* __restrict__ Ol, int K, int Nn) {
    __shared__ float tile[32][33];
    const int kb = blockIdx.x * 32;
    const int nb = blockIdx.y * 32;
    const int tx = threadIdx.x, ty = threadIdx.y;
#pragma unroll
    for (int j = 0; j < 4; ++j)
        tile[ty + j * 8][tx] = W[(size_t)(kb + ty + j * 8) * Nn + nb + tx];
    __syncthreads();
#pragma unroll
    for (int j = 0; j < 4; ++j) {
        int n = nb + ty + j * 8;
        float v = tile[tx][ty + j * 8];
        __nv_bfloat16 h = __float2bfloat16(v);
        Oh[(size_t)n * K + kb + tx] = h;
        Ol[(size_t)n * K + kb + tx] = __float2bfloat16(v - __bfloat162float(h));
    }
}

// ---------------- mma.sync bf16-split GEMM (f32 A input, fused attention dots) ---
#define GS_STRIDE 80                           // bytes per smem row (64B data + pad)
#define GS_PLANE  (128 * GS_STRIDE)            // 10240 B per matrix plane
#define GS_BUF    (4 * GS_PLANE)               // A_hi, A_lo, B_hi, B_lo
#define GS_SMEM   (2 * GS_BUF)                 // 81920 B double buffered

__device__ __forceinline__ void mma_bf16(float* c, const uint32_t* a, const uint32_t* b) {
    asm volatile(
        "mma.sync.aligned.m16n8k16.row.col.f32.bf16.bf16.f32 "
        "{%0,%1,%2,%3}, {%4,%5,%6,%7}, {%8,%9}, {%0,%1,%2,%3};"
        : "+f"(c[0]), "+f"(c[1]), "+f"(c[2]), "+f"(c[3])
        : "r"(a[0]), "r"(a[1]), "r"(a[2]), "r"(a[3]), "r"(b[0]), "r"(b[1]));
}
__device__ __forceinline__ uint32_t pack_bf(float a, float b) {
    __nv_bfloat162 p;
    p.x = __float2bfloat16(a);
    p.y = __float2bfloat16(b);
    return *reinterpret_cast<uint32_t*>(&p);
}

__global__ __launch_bounds__(128, 2)
void k_gemm_f32a(const float* __restrict__ A,
                 const __nv_bfloat16* __restrict__ Bh, const __nv_bfloat16* __restrict__ Bl,
                 const float* __restrict__ bias, float* __restrict__ C,
                 const float* __restrict__ att_s, const float* __restrict__ att_d,
                 float* __restrict__ es, float* __restrict__ ed, int es_stride,
                 int M, int Nn, int K) {
    extern __shared__ char smem[];
    const int t    = threadIdx.x;
    const int w    = t >> 5;
    const int lane = t & 31;
    const int g    = lane >> 2;
    const int tg   = lane & 3;
    const int wm   = w & 1;        // row slab (64 rows)
    const int wn   = w >> 1;       // col slab (64 cols)
    const int bx   = blockIdx.x;
    const int by   = blockIdx.y;

    float acc[4][8][4];
#pragma unroll
    for (int mi = 0; mi < 4; ++mi)
#pragma unroll
        for (int ni = 0; ni < 8; ++ni)
#pragma unroll
            for (int q = 0; q < 4; ++q) acc[mi][ni][q] = 0.f;

    const int nch = K >> 5;

    auto stage = [&](int bb, int c) {
        const int k0 = c << 5;
        char* base = smem + bb * GS_BUF;
#pragma unroll
        for (int i = 0; i < 4; ++i) {
            int u   = t + i * 128;
            int row = u >> 2;
            int q   = u & 3;
            int grow = by * 128 + row;
            float4 f0 = make_float4(0.f, 0.f, 0.f, 0.f);
            float4 f1 = make_float4(0.f, 0.f, 0.f, 0.f);
            if (grow < M) {
                const float* ap = A + (size_t)grow * K + k0 + q * 8;
                f0 = *reinterpret_cast<const float4*>(ap);
                f1 = *reinterpret_cast<const float4*>(ap + 4);
            }
            float vv[8] = {f0.x, f0.y, f0.z, f0.w, f1.x, f1.y, f1.z, f1.w};
            float rr[8];
#pragma unroll
            for (int j = 0; j < 8; ++j)
                rr[j] = vv[j] - __bfloat162float(__float2bfloat16(vv[j]));
            uint4 hv, lv;
            hv.x = pack_bf(vv[0], vv[1]); hv.y = pack_bf(vv[2], vv[3]);
            hv.z = pack_bf(vv[4], vv[5]); hv.w = pack_bf(vv[6], vv[7]);
            lv.x = pack_bf(rr[0], rr[1]); lv.y = pack_bf(rr[2], rr[3]);
            lv.z = pack_bf(rr[4], rr[5]); lv.w = pack_bf(rr[6], rr[7]);
            uint32_t so = row * GS_STRIDE + q * 16;
            *reinterpret_cast<uint4*>(base + so)            = hv;
            *reinterpret_cast<uint4*>(base + GS_PLANE + so) = lv;
            int nrow = bx * 128 + row;
            const size_t ob = (size_t)nrow * K + k0 + q * 8;
            uint4 wh = *reinterpret_cast<const uint4*>(Bh + ob);
            uint4 wl = *reinterpret_cast<const uint4*>(Bl + ob);
            *reinterpret_cast<uint4*>(base + 2 * GS_PLANE + so) = wh;
            *reinterpret_cast<uint4*>(base + 3 * GS_PLANE + so) = wl;
        }
    };

    stage(0, 0);
    __syncthreads();

    int bb = 0;
    for (int c = 0; c < nch; ++c) {
        if (c + 1 < nch) stage(bb ^ 1, c + 1);

        const char* Ahs = smem + bb * GS_BUF;
        const char* Als = Ahs + GS_PLANE;
        const char* Bhs = Ahs + 2 * GS_PLANE;
        const char* Bls = Ahs + 3 * GS_PLANE;

#pragma unroll
        for (int ks = 0; ks < 2; ++ks) {
            uint32_t ah[4][4], al[4][4];
#pragma unroll
            for (int mi = 0; mi < 4; ++mi) {
                uint32_t r0 = (wm * 64 + mi * 16 + g) * GS_STRIDE + ks * 32 + tg * 4;
                ah[mi][0] = *reinterpret_cast<const uint32_t*>(Ahs + r0);
                ah[mi][1] = *reinterpret_cast<const uint32_t*>(Ahs + r0 + 8 * GS_STRIDE);
                ah[mi][2] = *reinterpret_cast<const uint32_t*>(Ahs + r0 + 16);
                ah[mi][3] = *reinterpret_cast<const uint32_t*>(Ahs + r0 + 8 * GS_STRIDE + 16);
                al[mi][0] = *reinterpret_cast<const uint32_t*>(Als + r0);
                al[mi][1] = *reinterpret_cast<const uint32_t*>(Als + r0 + 8 * GS_STRIDE);
                al[mi][2] = *reinterpret_cast<const uint32_t*>(Als + r0 + 16);
                al[mi][3] = *reinterpret_cast<const uint32_t*>(Als + r0 + 8 * GS_STRIDE + 16);
            }
#pragma unroll
            for (int ni = 0; ni < 8; ++ni) {
                uint32_t n0 = (wn * 64 + ni * 8 + g) * GS_STRIDE + ks * 32 + tg * 4;
                uint32_t bh[2], bl[2];
                bh[0] = *reinterpret_cast<const uint32_t*>(Bhs + n0);
                bh[1] = *reinterpret_cast<const uint32_t*>(Bhs + n0 + 16);
                bl[0] = *reinterpret_cast<const uint32_t*>(Bls + n0);
                bl[1] = *reinterpret_cast<const uint32_t*>(Bls + n0 + 16);
#pragma unroll
                for (int mi = 0; mi < 4; ++mi) {
                    mma_bf16(acc[mi][ni], ah[mi], bh);
                    mma_bf16(acc[mi][ni], al[mi], bh);
                    mma_bf16(acc[mi][ni], ah[mi], bl);
                }
            }
        }
        __syncthreads();
        bb ^= 1;
    }

    // epilogue: f32 stores + fused attention dot partials (per-head = per block-x)
#pragma unroll
    for (int mi = 0; mi < 4; ++mi) {
        int r0 = by * 128 + wm * 64 + mi * 16 + g;
        float ps_a = 0.f, pd_a = 0.f, ps_b = 0.f, pd_b = 0.f;
#pragma unroll
        for (int ni = 0; ni < 8; ++ni) {
            int cc = bx * 128 + wn * 64 + ni * 8 + tg * 2;
            float b0 = bias ? bias[cc]     : 0.f;
            float b1 = bias ? bias[cc + 1] : 0.f;
            float v0 = acc[mi][ni][0] + b0, v1 = acc[mi][ni][1] + b1;
            float v2 = acc[mi][ni][2] + b0, v3 = acc[mi][ni][3] + b1;
            if (r0 < M)
                *reinterpret_cast<float2*>(C + (size_t)r0 * Nn + cc) = make_float2(v0, v1);
            if (r0 + 8 < M)
                *reinterpret_cast<float2*>(C + (size_t)(r0 + 8) * Nn + cc) = make_float2(v2, v3);
            if (es) {
                float s0 = att_s[cc], s1 = att_s[cc + 1];
                float d0 = att_d[cc], d1 = att_d[cc + 1];
                ps_a += v0 * s0 + v1 * s1;
                pd_a += v0 * d0 + v1 * d1;
                ps_b += v2 * s0 + v3 * s1;
                pd_b += v2 * d0 + v3 * d1;
            }
        }
        if (es) {
#pragma unroll
            for (int o = 1; o <= 2; o <<= 1) {
                ps_a += __shfl_xor_sync(0xffffffffu, ps_a, o);
                pd_a += __shfl_xor_sync(0xffffffffu, pd_a, o);
                ps_b += __shfl_xor_sync(0xffffffffu, ps_b, o);
                pd_b += __shfl_xor_sync(0xffffffffu, pd_b, o);
            }
            if (tg == 0) {
                if (r0 < M) {
                    atomicAdd(&es[(size_t)r0 * es_stride + bx], ps_a);
                    atomicAdd(&ed[(size_t)r0 * es_stride + bx], pd_a);
                }
                if (r0 + 8 < M) {
                    atomicAdd(&es[(size_t)(r0 + 8) * es_stride + bx], ps_b);
                    atomicAdd(&ed[(size_t)(r0 + 8) * es_stride + bx], pd_b);
                }
            }
        }
    }
}

// ---------------- fused softmax + aggregate, layer 1 (2 warps/node) -------------
// Warp j of a node handles channels [j*256, j*256+256) = heads 2j, 2j+1.
__global__ __launch_bounds__(256)
void k_agg1(const float* __restrict__ b1) {
    int gw   = (blockIdx.x * blockDim.x + threadIdx.x) >> 5;
    int node = gw >> 1;
    int wj   = gw & 1;
    int lane = threadIdx.x & 31;
    if (node >= NN) return;
    const int beg = g_rowptr[node];
    const int end = g_rowptr[node + 1];
    const float2 edv = *reinterpret_cast<const float2*>(g_ed1 + node * 4 + wj * 2);

    float mx0 = -1e30f, mx1 = -1e30f;
    for (int p = beg + lane; p < end; p += 32) {
        int s = g_ssrc[p];
        float2 esv = *reinterpret_cast<const float2*>(g_es1 + s * 4 + wj * 2);
        float e0 = esv.x + edv.x; e0 = (e0 >= 0.f) ? e0 : NEG * e0;
        float e1 = esv.y + edv.y; e1 = (e1 >= 0.f) ? e1 : NEG * e1;
        mx0 = fmaxf(mx0, e0);
        mx1 = fmaxf(mx1, e1);
    }
#pragma unroll
    for (int off = 16; off > 0; off >>= 1) {
        mx0 = fmaxf(mx0, __shfl_xor_sync(0xffffffffu, mx0, off));
        mx1 = fmaxf(mx1, __shfl_xor_sync(0xffffffffu, mx1, off));
    }

    float accv[8];
#pragma unroll
    for (int k = 0; k < 8; ++k) accv[k] = 0.f;
    float sm0 = 0.f, sm1 = 0.f;
    for (int p = beg; p < end; ++p) {
        int s = g_ssrc[p];
        float2 esv = *reinterpret_cast<const float2*>(g_es1 + s * 4 + wj * 2);
        float e0 = esv.x + edv.x; e0 = (e0 >= 0.f) ? e0 : NEG * e0;
        float e1 = esv.y + edv.y; e1 = (e1 >= 0.f) ? e1 : NEG * e1;
        float ex0 = __expf(e0 - mx0);
        float ex1 = __expf(e1 - mx1);
        sm0 += ex0;
        sm1 += ex1;
        const float* row = g_h1pre + (size_t)s * HC1 + wj * 256;
#pragma unroll
        for (int k = 0; k < 8; ++k)
            accv[k] += row[lane + 32 * k] * ((k < 4) ? ex0 : ex1);
    }
    float inv0 = 1.f / (sm0 + 1e-16f);
    float inv1 = 1.f / (sm1 + 1e-16f);
    float* outrow = g_h1out + (size_t)node * HC1 + wj * 256;
#pragma unroll
    for (int k = 0; k < 8; ++k) {
        int c = lane + 32 * k;
        float v = accv[k] * ((k < 4) ? inv0 : inv1) + b1[wj * 256 + c];
        v = (v > 0.f) ? v : expm1f(v);   // ELU
        outrow[c] = v;
    }
}

// ---------------- fused softmax + aggregate, layer 2 (2 warps/node) -------------
__global__ __launch_bounds__(256)
void k_agg2(const float* __restrict__ b2, float* __restrict__ out) {
    int gw   = (blockIdx.x * blockDim.x + threadIdx.x) >> 5;
    int node = gw >> 1;
    int wj   = gw & 1;
    int lane = threadIdx.x & 31;
    if (node >= NN) return;
    const int beg = g_rowptr[node];
    const int end = g_rowptr[node + 1];
    const float edv = g_ed2[node];

    float mx = -1e30f;
    for (int p = beg + lane; p < end; p += 32) {
        float e = g_es2[g_ssrc[p]] + edv;
        e = (e >= 0.f) ? e : NEG * e;
        mx = fmaxf(mx, e);
    }
#pragma unroll
    for (int off = 16; off > 0; off >>= 1)
        mx = fmaxf(mx, __shfl_xor_sync(0xffffffffu, mx, off));

    float acc0 = 0.f, acc1 = 0.f;
    float sm = 0.f;
    for (int p = beg; p < end; ++p) {
        int s = g_ssrc[p];
        float e = g_es2[s] + edv;
        e = (e >= 0.f) ? e : NEG * e;
        float ex = __expf(e - mx);
        sm += ex;
        const float* row = g_h2pre + (size_t)s * FOUT + wj * 64;
        acc0 += row[lane]      * ex;
        acc1 += row[lane + 32] * ex;
    }
    float inv = 1.f / (sm + 1e-16f);
    float* outrow = out + (size_t)node * FOUT + wj * 64;
    outrow[lane]      = acc0 * inv + b2[wj * 64 + lane];
    outrow[lane + 32] = acc1 * inv + b2[wj * 64 + lane + 32];
}

// ---------------- host launcher ----------------
extern "C" void kernel_launch(void* const* d_in, const int* in_sizes, int n_in,
                              void* d_out, int out_size) {
    const float* x    = (const float*)d_in[0];
    const int*   ei   = (const int*)d_in[1];
    const float* sent = (const float*)d_in[2];
    const float* W1   = (const float*)d_in[3];
    const float* a1s  = (const float*)d_in[4];
    const float* a1d  = (const float*)d_in[5];
    const float* b1   = (const float*)d_in[6];
    const float* W2   = (const float*)d_in[7];
    const float* a2s  = (const float*)d_in[8];
    const float* a2d  = (const float*)d_in[9];
    const float* b2   = (const float*)d_in[10];
    float* out = (float*)d_out;

    cudaFuncSetAttribute(k_gemm_f32a, cudaFuncAttributeMaxDynamicSharedMemorySize, GS_SMEM);

    float* h1pre; cudaGetSymbolAddress((void**)&h1pre, g_h1pre);
    float* h1out; cudaGetSymbolAddress((void**)&h1out, g_h1out);
    float* h2pre; cudaGetSymbolAddress((void**)&h2pre, g_h2pre);
    float* c1;    cudaGetSymbolAddress((void**)&c1,    g_c1);
    float* es1;   cudaGetSymbolAddress((void**)&es1,   g_es1);
    float* ed1;   cudaGetSymbolAddress((void**)&ed1,   g_ed1);
    float* es2;   cudaGetSymbolAddress((void**)&es2,   g_es2);
    float* ed2;   cudaGetSymbolAddress((void**)&ed2,   g_ed2);
    __nv_bfloat16 *w1thi, *w1tlo, *w2thi, *w2tlo;
    cudaGetSymbolAddress((void**)&w1thi, g_w1thi);
    cudaGetSymbolAddress((void**)&w1tlo, g_w1tlo);
    cudaGetSymbolAddress((void**)&w2thi, g_w2thi);
    cudaGetSymbolAddress((void**)&w2tlo, g_w2tlo);

    // zero + CSR build
    k_zero<<<(NN * H1 + 255) / 256, 256>>>();
    k_hist<<<(EE / 4 + 255) / 256, 256>>>(ei);
    k_scanA<<<SCAN_NB, 1024>>>();
    k_scanB<<<1, 32>>>();
    k_scanC<<<SCAN_NB, 1024>>>();
    k_scatter<<<(EE / 4 + 255) / 256, 256>>>(ei);

    // c1 = sent @ W1[768:]
    k_c1<<<SED / 16, 256>>>(sent, W1);

    // weight transpose+split (tiled, both sides coalesced)
    {
        dim3 blk(32, 8);
        dim3 g1(SED / 32, HC1 / 32);
        k_tsplit<<<g1, blk>>>(W1, w1thi, w1tlo, SED, HC1);   // W1 rows 0..767
        dim3 g2(HC1 / 32, FOUT / 32);
        k_tsplit<<<g2, blk>>>(W2, w2thi, w2tlo, HC1, FOUT);
    }

    // GEMM1: h1pre = x @ W1a + c1, fused es1/ed1 dots  (M=20000, N=512, K=768)
    {
        dim3 grid(HC1 / 128, (NN + 127) / 128);
        k_gemm_f32a<<<grid, 128, GS_SMEM>>>(x, w1thi, w1tlo, c1, h1pre,
                                            a1s, a1d, es1, ed1, H1, NN, HC1, SED);
    }

    k_agg1<<<(NN * 64 + 255) / 256, 256>>>(b1);

    // GEMM2: h2pre = h1out @ W2, fused es2/ed2 dots  (M=20000, N=128, K=512)
    {
        dim3 grid(FOUT / 128, (NN + 127) / 128);
        k_gemm_f32a<<<grid, 128, GS_SMEM>>>(h1out, w2thi, w2tlo, (const float*)nullptr, h2pre,
                                            a2s, a2d, es2, ed2, 1, NN, FOUT, HC1);
    }

    k_agg2<<<(NN * 64 + 255) / 256, 256>>>(b2, out);
}

// round 11
// speedup vs baseline: 1.0729x; 1.0729x over previous
#include <cuda_runtime.h>
#include <cuda_bf16.h>
#include <math.h>
#include <stdint.h>

// Problem constants (fixed by the dataset)
#define NN      20000
#define EE      320000
#define SED     768
#define HC1     512      // H1 * C1
#define H1      4
#define C1      128
#define FOUT    128
#define NEG     0.2f

// ---------------- device scratch (no allocation allowed) ----------------
__device__ float g_c1[HC1];                                 // sent @ W1[768:]
__device__ float g_h1pre[NN * HC1];                         // x @ W1a + c1 (f32)
__device__ float g_h1out[NN * HC1];                         // after GAT1 + bias + ELU (f32)
__device__ float g_h2pre[NN * FOUT];                        // h1out @ W2 (f32)
__device__ __align__(16) __nv_bfloat16 g_w1thi[HC1 * SED];  // W1a^T split hi  [512][768]
__device__ __align__(16) __nv_bfloat16 g_w1tlo[HC1 * SED];
__device__ __align__(16) __nv_bfloat16 g_w2thi[FOUT * HC1]; // W2^T split hi   [128][512]
__device__ __align__(16) __nv_bfloat16 g_w2tlo[FOUT * HC1];
__device__ __align__(16) float g_es1[NN * H1];
__device__ __align__(16) float g_ed1[NN * H1];
__device__ float g_es2[NN];
__device__ float g_ed2[NN];
__device__ int   g_deg[NN];
__device__ int   g_rowptr[NN + 1];
__device__ int   g_cur[NN];
__device__ int   g_ssrc[EE];                                // src node per dst-sorted edge slot

// ---------------- zero / CSR build ----------------
__global__ void k_zero() {
    int i = blockIdx.x * blockDim.x + threadIdx.x;
    if (i < NN) {
        g_deg[i] = 0;
        g_es2[i] = 0.f;
        g_ed2[i] = 0.f;
    }
    if (i < HC1) g_c1[i] = 0.f;
    if (i < NN * H1) { g_es1[i] = 0.f; g_ed1[i] = 0.f; }
}
__global__ void k_hist(const int* __restrict__ ei) {
    int e = blockIdx.x * blockDim.x + threadIdx.x;
    if (e < EE) atomicAdd(&g_deg[ei[EE + e]], 1);
}
__global__ void k_scan() {
    __shared__ int wsum[32];
    __shared__ int ctot;
    const int t = threadIdx.x, lane = t & 31, wid = t >> 5;
    int carry = 0;
    for (int base = 0; base < NN; base += 1024) {
        int i = base + t;
        int v = (i < NN) ? g_deg[i] : 0;
        int incl = v;
#pragma unroll
        for (int o = 1; o < 32; o <<= 1) {
            int x = __shfl_up_sync(0xffffffffu, incl, o);
            if (lane >= o) incl += x;
        }
        if (lane == 31) wsum[wid] = incl;
        __syncthreads();
        if (wid == 0) {
            int s = wsum[lane];
#pragma unroll
            for (int o = 1; o < 32; o <<= 1) {
                int x = __shfl_up_sync(0xffffffffu, s, o);
                if (lane >= o) s += x;
            }
            wsum[lane] = s;
            if (lane == 31) ctot = s;
        }
        __syncthreads();
        int off = wid ? wsum[wid - 1] : 0;
        if (i < NN) {
            int ex = carry + off + incl - v;
            g_rowptr[i] = ex;
            g_cur[i] = ex;
        }
        carry += ctot;
        __syncthreads();
    }
    if (t == 0) g_rowptr[NN] = carry;
}
__global__ void k_scatter(const int* __restrict__ ei) {
    int e = blockIdx.x * blockDim.x + threadIdx.x;
    if (e < EE) {
        int src = ei[e];
        int dst = ei[EE + e];
        int p = atomicAdd(&g_cur[dst], 1);
        g_ssrc[p] = src;
    }
}

// ---------------- c1 = sent @ W1[768:, :]  (48 blocks x 16 k-rows) ----------------
__global__ void k_c1(const float* __restrict__ sent, const float* __restrict__ W1) {
    const int b = blockIdx.x;
    const int t = threadIdx.x;
    const float* Wb = W1 + (size_t)(SED + b * 16) * HC1;
    float a0 = 0.f, a1 = 0.f;
#pragma unroll
    for (int k = 0; k < 16; ++k) {
        float s = sent[b * 16 + k];
        a0 += s * Wb[k * HC1 + t];
        a1 += s * Wb[k * HC1 + t + 256];
    }
    atomicAdd(&g_c1[t], a0);
    atomicAdd(&g_c1[t + 256], a1);
}

// ---------------- tiled transpose + split:  Out[n][k] = W[k][n] ----------------
// blockDim (32, 8); each block handles a 32x32 tile. Both gmem sides coalesced.
__global__ void k_tsplit(const float* __restrict__ W, __nv_bfloat16* __restrict__ Oh,
                         __nv_bfloat16* __restrict__ Ol, int K, int Nn) {
    __shared__ float tile[32][33];
    const int kb = blockIdx.x * 32;
    const int nb = blockIdx.y * 32;
    const int tx = threadIdx.x, ty = threadIdx.y;
#pragma unroll
    for (int j = 0; j < 4; ++j)
        tile[ty + j * 8][tx] = W[(size_t)(kb + ty + j * 8) * Nn + nb + tx];
    __syncthreads();
#pragma unroll
    for (int j = 0; j < 4; ++j) {
        int n = nb + ty + j * 8;
        float v = tile[tx][ty + j * 8];
        __nv_bfloat16 h = __float2bfloat16(v);
        Oh[(size_t)n * K + kb + tx] = h;
        Ol[(size_t)n * K + kb + tx] = __float2bfloat16(v - __bfloat162float(h));
    }
}

// ---------------- mma.sync bf16-split GEMM (f32 A input, fused attention dots) ---
// C[M,Nn] = A[M,K] * (Bh+Bl)^T   with Bt stored [Nn][K] row-major (K contiguous)
// A converted to bf16 hi/lo in-register during staging.
// Block tile 128x128, BK=32, 4 warps of 64x64 warp tiles, double-buffered smem.
#define GS_STRIDE 80                           // bytes per smem row (64B data + pad)
#define GS_PLANE  (128 * GS_STRIDE)            // 10240 B per matrix plane
#define GS_BUF    (4 * GS_PLANE)               // A_hi, A_lo, B_hi, B_lo
#define GS_SMEM   (2 * GS_BUF)                 // 81920 B double buffered

__device__ __forceinline__ void mma_bf16(float* c, const uint32_t* a, const uint32_t* b) {
    asm volatile(
        "mma.sync.aligned.m16n8k16.row.col.f32.bf16.bf16.f32 "
        "{%0,%1,%2,%3}, {%4,%5,%6,%7}, {%8,%9}, {%0,%1,%2,%3};"
        : "+f"(c[0]), "+f"(c[1]), "+f"(c[2]), "+f"(c[3])
        : "r"(a[0]), "r"(a[1]), "r"(a[2]), "r"(a[3]), "r"(b[0]), "r"(b[1]));
}
__device__ __forceinline__ uint32_t pack_bf(float a, float b) {
    __nv_bfloat162 p;
    p.x = __float2bfloat16(a);
    p.y = __float2bfloat16(b);
    return *reinterpret_cast<uint32_t*>(&p);
}

__global__ __launch_bounds__(128, 2)
void k_gemm_f32a(const float* __restrict__ A,
                 const __nv_bfloat16* __restrict__ Bh, const __nv_bfloat16* __restrict__ Bl,
                 const float* __restrict__ bias, float* __restrict__ C,
                 const float* __restrict__ att_s, const float* __restrict__ att_d,
                 float* __restrict__ es, float* __restrict__ ed, int es_stride,
                 int M, int Nn, int K) {
    extern __shared__ char smem[];
    const int t    = threadIdx.x;
    const int w    = t >> 5;
    const int lane = t & 31;
    const int g    = lane >> 2;
    const int tg   = lane & 3;
    const int wm   = w & 1;        // row slab (64 rows)
    const int wn   = w >> 1;       // col slab (64 cols)
    const int bx   = blockIdx.x;
    const int by   = blockIdx.y;

    float acc[4][8][4];
#pragma unroll
    for (int mi = 0; mi < 4; ++mi)
#pragma unroll
        for (int ni = 0; ni < 8; ++ni)
#pragma unroll
            for (int q = 0; q < 4; ++q) acc[mi][ni][q] = 0.f;

    const int nch = K >> 5;

    auto stage = [&](int bb, int c) {
        const int k0 = c << 5;
        char* base = smem + bb * GS_BUF;
#pragma unroll
        for (int i = 0; i < 4; ++i) {
            int u   = t + i * 128;
            int row = u >> 2;
            int q   = u & 3;
            // A: load f32, convert to hi/lo bf16
            int grow = by * 128 + row;
            float4 f0 = make_float4(0.f, 0.f, 0.f, 0.f);
            float4 f1 = make_float4(0.f, 0.f, 0.f, 0.f);
            if (grow < M) {
                const float* ap = A + (size_t)grow * K + k0 + q * 8;
                f0 = *reinterpret_cast<const float4*>(ap);
                f1 = *reinterpret_cast<const float4*>(ap + 4);
            }
            float vv[8] = {f0.x, f0.y, f0.z, f0.w, f1.x, f1.y, f1.z, f1.w};
            float rr[8];
#pragma unroll
            for (int j = 0; j < 8; ++j)
                rr[j] = vv[j] - __bfloat162float(__float2bfloat16(vv[j]));
            uint4 hv, lv;
            hv.x = pack_bf(vv[0], vv[1]); hv.y = pack_bf(vv[2], vv[3]);
            hv.z = pack_bf(vv[4], vv[5]); hv.w = pack_bf(vv[6], vv[7]);
            lv.x = pack_bf(rr[0], rr[1]); lv.y = pack_bf(rr[2], rr[3]);
            lv.z = pack_bf(rr[4], rr[5]); lv.w = pack_bf(rr[6], rr[7]);
            uint32_t so = row * GS_STRIDE + q * 16;
            *reinterpret_cast<uint4*>(base + so)            = hv;
            *reinterpret_cast<uint4*>(base + GS_PLANE + so) = lv;
            // B: presplit bf16 (Nn multiple of 128 -> always valid)
            int nrow = bx * 128 + row;
            const size_t ob = (size_t)nrow * K + k0 + q * 8;
            uint4 wh = *reinterpret_cast<const uint4*>(Bh + ob);
            uint4 wl = *reinterpret_cast<const uint4*>(Bl + ob);
            *reinterpret_cast<uint4*>(base + 2 * GS_PLANE + so) = wh;
            *reinterpret_cast<uint4*>(base + 3 * GS_PLANE + so) = wl;
        }
    };

    stage(0, 0);
    __syncthreads();

    int bb = 0;
    for (int c = 0; c < nch; ++c) {
        if (c + 1 < nch) stage(bb ^ 1, c + 1);

        const char* Ahs = smem + bb * GS_BUF;
        const char* Als = Ahs + GS_PLANE;
        const char* Bhs = Ahs + 2 * GS_PLANE;
        const char* Bls = Ahs + 3 * GS_PLANE;

#pragma unroll
        for (int ks = 0; ks < 2; ++ks) {
            uint32_t ah[4][4], al[4][4];
#pragma unroll
            for (int mi = 0; mi < 4; ++mi) {
                uint32_t r0 = (wm * 64 + mi * 16 + g) * GS_STRIDE + ks * 32 + tg * 4;
                ah[mi][0] = *reinterpret_cast<const uint32_t*>(Ahs + r0);
                ah[mi][1] = *reinterpret_cast<const uint32_t*>(Ahs + r0 + 8 * GS_STRIDE);
                ah[mi][2] = *reinterpret_cast<const uint32_t*>(Ahs + r0 + 16);
                ah[mi][3] = *reinterpret_cast<const uint32_t*>(Ahs + r0 + 8 * GS_STRIDE + 16);
                al[mi][0] = *reinterpret_cast<const uint32_t*>(Als + r0);
                al[mi][1] = *reinterpret_cast<const uint32_t*>(Als + r0 + 8 * GS_STRIDE);
                al[mi][2] = *reinterpret_cast<const uint32_t*>(Als + r0 + 16);
                al[mi][3] = *reinterpret_cast<const uint32_t*>(Als + r0 + 8 * GS_STRIDE + 16);
            }
#pragma unroll
            for (int ni = 0; ni < 8; ++ni) {
                uint32_t n0 = (wn * 64 + ni * 8 + g) * GS_STRIDE + ks * 32 + tg * 4;
                uint32_t bh[2], bl[2];
                bh[0] = *reinterpret_cast<const uint32_t*>(Bhs + n0);
                bh[1] = *reinterpret_cast<const uint32_t*>(Bhs + n0 + 16);
                bl[0] = *reinterpret_cast<const uint32_t*>(Bls + n0);
                bl[1] = *reinterpret_cast<const uint32_t*>(Bls + n0 + 16);
#pragma unroll
                for (int mi = 0; mi < 4; ++mi) {
                    mma_bf16(acc[mi][ni], ah[mi], bh);
                    mma_bf16(acc[mi][ni], al[mi], bh);
                    mma_bf16(acc[mi][ni], ah[mi], bl);
                }
            }
        }
        __syncthreads();
        bb ^= 1;
    }

    // epilogue: f32 stores + fused attention dot partials (per-head = per block-x)
#pragma unroll
    for (int mi = 0; mi < 4; ++mi) {
        int r0 = by * 128 + wm * 64 + mi * 16 + g;
        float ps_a = 0.f, pd_a = 0.f, ps_b = 0.f, pd_b = 0.f;
#pragma unroll
        for (int ni = 0; ni < 8; ++ni) {
            int cc = bx * 128 + wn * 64 + ni * 8 + tg * 2;
            float b0 = bias ? bias[cc]     : 0.f;
            float b1 = bias ? bias[cc + 1] : 0.f;
            float v0 = acc[mi][ni][0] + b0, v1 = acc[mi][ni][1] + b1;
            float v2 = acc[mi][ni][2] + b0, v3 = acc[mi][ni][3] + b1;
            if (r0 < M)
                *reinterpret_cast<float2*>(C + (size_t)r0 * Nn + cc) = make_float2(v0, v1);
            if (r0 + 8 < M)
                *reinterpret_cast<float2*>(C + (size_t)(r0 + 8) * Nn + cc) = make_float2(v2, v3);
            if (es) {
                float s0 = att_s[cc], s1 = att_s[cc + 1];
                float d0 = att_d[cc], d1 = att_d[cc + 1];
                ps_a += v0 * s0 + v1 * s1;
                pd_a += v0 * d0 + v1 * d1;
                ps_b += v2 * s0 + v3 * s1;
                pd_b += v2 * d0 + v3 * d1;
            }
        }
        if (es) {
#pragma unroll
            for (int o = 1; o <= 2; o <<= 1) {
                ps_a += __shfl_xor_sync(0xffffffffu, ps_a, o);
                pd_a += __shfl_xor_sync(0xffffffffu, pd_a, o);
                ps_b += __shfl_xor_sync(0xffffffffu, ps_b, o);
                pd_b += __shfl_xor_sync(0xffffffffu, pd_b, o);
            }
            if (tg == 0) {
                if (r0 < M) {
                    atomicAdd(&es[(size_t)r0 * es_stride + bx], ps_a);
                    atomicAdd(&ed[(size_t)r0 * es_stride + bx], pd_a);
                }
                if (r0 + 8 < M) {
                    atomicAdd(&es[(size_t)(r0 + 8) * es_stride + bx], ps_b);
                    atomicAdd(&ed[(size_t)(r0 + 8) * es_stride + bx], pd_b);
                }
            }
        }
    }
}

// ---------------- fused softmax + aggregate, layer 1 (edge loop unrolled x2) ----
__global__ __launch_bounds__(256)
void k_agg1(const float* __restrict__ b1) {
    int warp = (blockIdx.x * blockDim.x + threadIdx.x) >> 5;
    int lane = threadIdx.x & 31;
    if (warp >= NN) return;
    const int beg = g_rowptr[warp];
    const int end = g_rowptr[warp + 1];
    float edv[H1];
#pragma unroll
    for (int h = 0; h < H1; ++h) edv[h] = g_ed1[warp * H1 + h];

    // pass A: per-head max (lane-distributed)
    float mx[H1] = {-1e30f, -1e30f, -1e30f, -1e30f};
    for (int p = beg + lane; p < end; p += 32) {
        int s = g_ssrc[p];
        float4 esv = *reinterpret_cast<const float4*>(g_es1 + s * 4);
        float ev[H1] = {esv.x, esv.y, esv.z, esv.w};
#pragma unroll
        for (int h = 0; h < H1; ++h) {
            float e = ev[h] + edv[h];
            e = (e >= 0.f) ? e : NEG * e;
            mx[h] = fmaxf(mx[h], e);
        }
    }
#pragma unroll
    for (int h = 0; h < H1; ++h)
#pragma unroll
        for (int off = 16; off > 0; off >>= 1)
            mx[h] = fmaxf(mx[h], __shfl_xor_sync(0xffffffffu, mx[h], off));

    // pass B: weighted accumulation, unrolled x2 (two independent gather chains)
    float accv[16];
#pragma unroll
    for (int k = 0; k < 16; ++k) accv[k] = 0.f;
    float sm[H1] = {0.f, 0.f, 0.f, 0.f};
    int p = beg;
    for (; p + 2 <= end; p += 2) {
        int s0 = g_ssrc[p];
        int s1 = g_ssrc[p + 1];
        float4 e0v = *reinterpret_cast<const float4*>(g_es1 + s0 * 4);
        float4 e1v = *reinterpret_cast<const float4*>(g_es1 + s1 * 4);
        float ev0[H1] = {e0v.x, e0v.y, e0v.z, e0v.w};
        float ev1[H1] = {e1v.x, e1v.y, e1v.z, e1v.w};
        float ex0[H1], ex1[H1];
#pragma unroll
        for (int h = 0; h < H1; ++h) {
            float a = ev0[h] + edv[h];
            a = (a >= 0.f) ? a : NEG * a;
            ex0[h] = __expf(a - mx[h]);
            float b = ev1[h] + edv[h];
            b = (b >= 0.f) ? b : NEG * b;
            ex1[h] = __expf(b - mx[h]);
            sm[h] += ex0[h] + ex1[h];
        }
        const float* r0 = g_h1pre + (size_t)s0 * HC1;
        const float* r1 = g_h1pre + (size_t)s1 * HC1;
#pragma unroll
        for (int k = 0; k < 16; ++k) {
            int c = lane + 32 * k;
            int h = k >> 2;
            accv[k] += r0[c] * ex0[h] + r1[c] * ex1[h];
        }
    }
    if (p < end) {
        int s = g_ssrc[p];
        float4 esv = *reinterpret_cast<const float4*>(g_es1 + s * 4);
        float ev[H1] = {esv.x, esv.y, esv.z, esv.w};
        float ex[H1];
#pragma unroll
        for (int h = 0; h < H1; ++h) {
            float e = ev[h] + edv[h];
            e = (e >= 0.f) ? e : NEG * e;
            ex[h] = __expf(e - mx[h]);
            sm[h] += ex[h];
        }
        const float* row = g_h1pre + (size_t)s * HC1;
#pragma unroll
        for (int k = 0; k < 16; ++k)
            accv[k] += row[lane + 32 * k] * ex[k >> 2];
    }
#pragma unroll
    for (int k = 0; k < 16; ++k) {
        int c = lane + 32 * k;
        int h = k >> 2;
        float v = accv[k] / (sm[h] + 1e-16f) + b1[c];
        v = (v > 0.f) ? v : expm1f(v);   // ELU
        g_h1out[(size_t)warp * HC1 + c] = v;
    }
}

// ---------------- fused softmax + aggregate, layer 2 (edge loop unrolled x2) ----
__global__ __launch_bounds__(256)
void k_agg2(const float* __restrict__ b2, float* __restrict__ out) {
    int warp = (blockIdx.x * blockDim.x + threadIdx.x) >> 5;
    int lane = threadIdx.x & 31;
    if (warp >= NN) return;
    const int beg = g_rowptr[warp];
    const int end = g_rowptr[warp + 1];
    const float edv = g_ed2[warp];

    float mx = -1e30f;
    for (int p = beg + lane; p < end; p += 32) {
        float e = g_es2[g_ssrc[p]] + edv;
        e = (e >= 0.f) ? e : NEG * e;
        mx = fmaxf(mx, e);
    }
#pragma unroll
    for (int off = 16; off > 0; off >>= 1)
        mx = fmaxf(mx, __shfl_xor_sync(0xffffffffu, mx, off));

    float accv[4] = {0.f, 0.f, 0.f, 0.f};
    float sm = 0.f;
    int p = beg;
    for (; p + 2 <= end; p += 2) {
        int s0 = g_ssrc[p];
        int s1 = g_ssrc[p + 1];
        float a = g_es2[s0] + edv;
        a = (a >= 0.f) ? a : NEG * a;
        float b = g_es2[s1] + edv;
        b = (b >= 0.f) ? b : NEG * b;
        float ex0 = __expf(a - mx);
        float ex1 = __expf(b - mx);
        sm += ex0 + ex1;
        const float* r0 = g_h2pre + (size_t)s0 * FOUT;
        const float* r1 = g_h2pre + (size_t)s1 * FOUT;
#pragma unroll
        for (int k = 0; k < 4; ++k) {
            int c = lane + 32 * k;
            accv[k] += r0[c] * ex0 + r1[c] * ex1;
        }
    }
    if (p < end) {
        int s = g_ssrc[p];
        float e = g_es2[s] + edv;
        e = (e >= 0.f) ? e : NEG * e;
        float ex = __expf(e - mx);
        sm += ex;
        const float* row = g_h2pre + (size_t)s * FOUT;
#pragma unroll
        for (int k = 0; k < 4; ++k)
            accv[k] += row[lane + 32 * k] * ex;
    }
    float* outrow = out + (size_t)warp * FOUT;
    float inv = 1.f / (sm + 1e-16f);
#pragma unroll
    for (int k = 0; k < 4; ++k) {
        int c = lane + 32 * k;
        outrow[c] = accv[k] * inv + b2[c];
    }
}

// ---------------- host launcher ----------------
extern "C" void kernel_launch(void* const* d_in, const int* in_sizes, int n_in,
                              void* d_out, int out_size) {
    const float* x    = (const float*)d_in[0];
    const int*   ei   = (const int*)d_in[1];
    const float* sent = (const float*)d_in[2];
    const float* W1   = (const float*)d_in[3];
    const float* a1s  = (const float*)d_in[4];
    const float* a1d  = (const float*)d_in[5];
    const float* b1   = (const float*)d_in[6];
    const float* W2   = (const float*)d_in[7];
    const float* a2s  = (const float*)d_in[8];
    const float* a2d  = (const float*)d_in[9];
    const float* b2   = (const float*)d_in[10];
    float* out = (float*)d_out;

    cudaFuncSetAttribute(k_gemm_f32a, cudaFuncAttributeMaxDynamicSharedMemorySize, GS_SMEM);

    float* h1pre; cudaGetSymbolAddress((void**)&h1pre, g_h1pre);
    float* h1out; cudaGetSymbolAddress((void**)&h1out, g_h1out);
    float* h2pre; cudaGetSymbolAddress((void**)&h2pre, g_h2pre);
    float* c1;    cudaGetSymbolAddress((void**)&c1,    g_c1);
    float* es1;   cudaGetSymbolAddress((void**)&es1,   g_es1);
    float* ed1;   cudaGetSymbolAddress((void**)&ed1,   g_ed1);
    float* es2;   cudaGetSymbolAddress((void**)&es2,   g_es2);
    float* ed2;   cudaGetSymbolAddress((void**)&ed2,   g_ed2);
    __nv_bfloat16 *w1thi, *w1tlo, *w2thi, *w2tlo;
    cudaGetSymbolAddress((void**)&w1thi, g_w1thi);
    cudaGetSymbolAddress((void**)&w1tlo, g_w1tlo);
    cudaGetSymbolAddress((void**)&w2thi, g_w2thi);
    cudaGetSymbolAddress((void**)&w2tlo, g_w2tlo);

    // zero + CSR build
    k_zero<<<(NN * H1 + 255) / 256, 256>>>();
    k_hist<<<(EE + 255) / 256, 256>>>(ei);
    k_scan<<<1, 1024>>>();
    k_scatter<<<(EE + 255) / 256, 256>>>(ei);

    // c1 = sent @ W1[768:]
    k_c1<<<SED / 16, 256>>>(sent, W1);

    // weight transpose+split (tiled, both sides coalesced)
    {
        dim3 blk(32, 8);
        dim3 g1(SED / 32, HC1 / 32);
        k_tsplit<<<g1, blk>>>(W1, w1thi, w1tlo, SED, HC1);   // W1 rows 0..767
        dim3 g2(HC1 / 32, FOUT / 32);
        k_tsplit<<<g2, blk>>>(W2, w2thi, w2tlo, HC1, FOUT);
    }

    // GEMM1: h1pre = x @ W1a + c1, fused es1/ed1 dots  (M=20000, N=512, K=768)
    {
        dim3 grid(HC1 / 128, (NN + 127) / 128);
        k_gemm_f32a<<<grid, 128, GS_SMEM>>>(x, w1thi, w1tlo, c1, h1pre,
                                            a1s, a1d, es1, ed1, H1, NN, HC1, SED);
    }

    k_agg1<<<(NN * 32 + 255) / 256, 256>>>(b1);

    // GEMM2: h2pre = h1out @ W2, fused es2/ed2 dots  (M=20000, N=128, K=512)
    {
        dim3 grid(FOUT / 128, (NN + 127) / 128);
        k_gemm_f32a<<<grid, 128, GS_SMEM>>>(h1out, w2thi, w2tlo, (const float*)nullptr, h2pre,
                                            a2s, a2d, es2, ed2, 1, NN, FOUT, HC1);
    }

    k_agg2<<<(NN * 32 + 255) / 256, 256>>>(b2, out);
}

// round 15
// speedup vs baseline: 1.1590x; 1.0802x over previous
#include <cuda_runtime.h>
#include <cuda_bf16.h>
#include <math.h>
#include <stdint.h>

// Problem constants (fixed by the dataset)
#define NN      20000
#define EE      320000
#define SED     768
#define HC1     512      // H1 * C1
#define H1      4
#define C1      128
#define FOUT    128
#define NEG     0.2f

// ---------------- device scratch (no allocation allowed) ----------------
__device__ float g_c1[HC1];                                 // sent @ W1[768:]
__device__ float g_h1pre[NN * HC1];                         // x @ W1a + c1 (f32)
__device__ float g_h1out[NN * HC1];                         // after GAT1 + bias + ELU (f32)
__device__ float g_h2pre[NN * FOUT];                        // h1out @ W2 (f32)
__device__ __align__(16) __nv_bfloat16 g_w1thi[HC1 * SED];  // W1a^T split hi  [512][768]
__device__ __align__(16) __nv_bfloat16 g_w1tlo[HC1 * SED];
__device__ __align__(16) __nv_bfloat16 g_w2thi[FOUT * HC1]; // W2^T split hi   [128][512]
__device__ __align__(16) __nv_bfloat16 g_w2tlo[FOUT * HC1];
__device__ __align__(16) float g_es1[NN * H1];
__device__ __align__(16) float g_ed1[NN * H1];
__device__ float g_es2[NN];
__device__ float g_ed2[NN];
__device__ int   g_deg[NN];
__device__ int   g_rowptr[NN + 1];
__device__ int   g_cur[NN];
__device__ int   g_ssrc[EE];                                // src node per dst-sorted edge slot

// ---------------- zero / CSR build ----------------
__global__ void k_zero() {
    int i = blockIdx.x * blockDim.x + threadIdx.x;
    if (i < NN) {
        g_deg[i] = 0;
        g_es2[i] = 0.f;
        g_ed2[i] = 0.f;
    }
    if (i < HC1) g_c1[i] = 0.f;
    if (i < NN * H1) { g_es1[i] = 0.f; g_ed1[i] = 0.f; }
}
__global__ void k_hist(const int* __restrict__ ei) {
    int e = blockIdx.x * blockDim.x + threadIdx.x;
    if (e < EE) atomicAdd(&g_deg[ei[EE + e]], 1);
}
__global__ void k_scan() {
    __shared__ int wsum[32];
    __shared__ int ctot;
    const int t = threadIdx.x, lane = t & 31, wid = t >> 5;
    int carry = 0;
    for (int base = 0; base < NN; base += 1024) {
        int i = base + t;
        int v = (i < NN) ? g_deg[i] : 0;
        int incl = v;
#pragma unroll
        for (int o = 1; o < 32; o <<= 1) {
            int x = __shfl_up_sync(0xffffffffu, incl, o);
            if (lane >= o) incl += x;
        }
        if (lane == 31) wsum[wid] = incl;
        __syncthreads();
        if (wid == 0) {
            int s = wsum[lane];
#pragma unroll
            for (int o = 1; o < 32; o <<= 1) {
                int x = __shfl_up_sync(0xffffffffu, s, o);
                if (lane >= o) s += x;
            }
            wsum[lane] = s;
            if (lane == 31) ctot = s;
        }
        __syncthreads();
        int off = wid ? wsum[wid - 1] : 0;
        if (i < NN) {
            int ex = carry + off + incl - v;
            g_rowptr[i] = ex;
            g_cur[i] = ex;
        }
        carry += ctot;
        __syncthreads();
    }
    if (t == 0) g_rowptr[NN] = carry;
}
__global__ void k_scatter(const int* __restrict__ ei) {
    int e = blockIdx.x * blockDim.x + threadIdx.x;
    if (e < EE) {
        int src = ei[e];
        int dst = ei[EE + e];
        int p = atomicAdd(&g_cur[dst], 1);
        g_ssrc[p] = src;
    }
}

// ---------------- c1 = sent @ W1[768:, :]  (48 blocks x 16 k-rows) ----------------
__global__ void k_c1(const float* __restrict__ sent, const float* __restrict__ W1) {
    const int b = blockIdx.x;
    const int t = threadIdx.x;
    const float* Wb = W1 + (size_t)(SED + b * 16) * HC1;
    float a0 = 0.f, a1 = 0.f;
#pragma unroll
    for (int k = 0; k < 16; ++k) {
        float s = sent[b * 16 + k];
        a0 += s * Wb[k * HC1 + t];
        a1 += s * Wb[k * HC1 + t + 256];
    }
    atomicAdd(&g_c1[t], a0);
    atomicAdd(&g_c1[t + 256], a1);
}

// ---------------- tiled transpose + split:  Out[n][k] = W[k][n] ----------------
__global__ void k_tsplit(const float* __restrict__ W, __nv_bfloat16* __restrict__ Oh,
                         __nv_bfloat16* __restrict__ Ol, int K, int Nn) {
    __shared__ float tile[32][33];
    const int kb = blockIdx.x * 32;
    const int nb = blockIdx.y * 32;
    const int tx = threadIdx.x, ty = threadIdx.y;
#pragma unroll
    for (int j = 0; j < 4; ++j)
        tile[ty + j * 8][tx] = W[(size_t)(kb + ty + j * 8) * Nn + nb + tx];
    __syncthreads();
#pragma unroll
    for (int j = 0; j < 4; ++j) {
        int n = nb + ty + j * 8;
        float v = tile[tx][ty + j * 8];
        __nv_bfloat16 h = __float2bfloat16(v);
        Oh[(size_t)n * K + kb + tx] = h;
        Ol[(size_t)n * K + kb + tx] = __float2bfloat16(v - __bfloat162float(h));
    }
}

// ---------------- mma.sync bf16-split GEMM (f32 A input, fused attention dots) ---
#define GS_STRIDE 80                           // bytes per smem row (64B data + pad)
#define GS_PLANE  (128 * GS_STRIDE)            // 10240 B per matrix plane
#define GS_BUF    (4 * GS_PLANE)               // A_hi, A_lo, B_hi, B_lo
#define GS_SMEM   (2 * GS_BUF)                 // 81920 B double buffered

__device__ __forceinline__ void mma_bf16(float* c, const uint32_t* a, const uint32_t* b) {
    asm volatile(
        "mma.sync.aligned.m16n8k16.row.col.f32.bf16.bf16.f32 "
        "{%0,%1,%2,%3}, {%4,%5,%6,%7}, {%8,%9}, {%0,%1,%2,%3};"
        : "+f"(c[0]), "+f"(c[1]), "+f"(c[2]), "+f"(c[3])
        : "r"(a[0]), "r"(a[1]), "r"(a[2]), "r"(a[3]), "r"(b[0]), "r"(b[1]));
}
__device__ __forceinline__ uint32_t pack_bf(float a, float b) {
    __nv_bfloat162 p;
    p.x = __float2bfloat16(a);
    p.y = __float2bfloat16(b);
    return *reinterpret_cast<uint32_t*>(&p);
}

__global__ __launch_bounds__(128, 2)
void k_gemm_f32a(const float* __restrict__ A,
                 const __nv_bfloat16* __restrict__ Bh, const __nv_bfloat16* __restrict__ Bl,
                 const float* __restrict__ bias, float* __restrict__ C,
                 const float* __restrict__ att_s, const float* __restrict__ att_d,
                 float* __restrict__ es, float* __restrict__ ed, int es_stride,
                 int M, int Nn, int K) {
    extern __shared__ char smem[];
    const int t    = threadIdx.x;
    const int w    = t >> 5;
    const int lane = t & 31;
    const int g    = lane >> 2;
    const int tg   = lane & 3;
    const int wm   = w & 1;        // row slab (64 rows)
    const int wn   = w >> 1;       // col slab (64 cols)
    const int bx   = blockIdx.x;
    const int by   = blockIdx.y;

    float acc[4][8][4];
#pragma unroll
    for (int mi = 0; mi < 4; ++mi)
#pragma unroll
        for (int ni = 0; ni < 8; ++ni)
#pragma unroll
            for (int q = 0; q < 4; ++q) acc[mi][ni][q] = 0.f;

    const int nch = K >> 5;

    auto stage = [&](int bb, int c) {
        const int k0 = c << 5;
        char* base = smem + bb * GS_BUF;
#pragma unroll
        for (int i = 0; i < 4; ++i) {
            int u   = t + i * 128;
            int row = u >> 2;
            int q   = u & 3;
            int grow = by * 128 + row;
            float4 f0 = make_float4(0.f, 0.f, 0.f, 0.f);
            float4 f1 = make_float4(0.f, 0.f, 0.f, 0.f);
            if (grow < M) {
                const float* ap = A + (size_t)grow * K + k0 + q * 8;
                f0 = *reinterpret_cast<const float4*>(ap);
                f1 = *reinterpret_cast<const float4*>(ap + 4);
            }
            float vv[8] = {f0.x, f0.y, f0.z, f0.w, f1.x, f1.y, f1.z, f1.w};
            float rr[8];
#pragma unroll
            for (int j = 0; j < 8; ++j)
                rr[j] = vv[j] - __bfloat162float(__float2bfloat16(vv[j]));
            uint4 hv, lv;
            hv.x = pack_bf(vv[0], vv[1]); hv.y = pack_bf(vv[2], vv[3]);
            hv.z = pack_bf(vv[4], vv[5]); hv.w = pack_bf(vv[6], vv[7]);
            lv.x = pack_bf(rr[0], rr[1]); lv.y = pack_bf(rr[2], rr[3]);
            lv.z = pack_bf(rr[4], rr[5]); lv.w = pack_bf(rr[6], rr[7]);
            uint32_t so = row * GS_STRIDE + q * 16;
            *reinterpret_cast<uint4*>(base + so)            = hv;
            *reinterpret_cast<uint4*>(base + GS_PLANE + so) = lv;
            int nrow = bx * 128 + row;
            const size_t ob = (size_t)nrow * K + k0 + q * 8;
            uint4 wh = *reinterpret_cast<const uint4*>(Bh + ob);
            uint4 wl = *reinterpret_cast<const uint4*>(Bl + ob);
            *reinterpret_cast<uint4*>(base + 2 * GS_PLANE + so) = wh;
            *reinterpret_cast<uint4*>(base + 3 * GS_PLANE + so) = wl;
        }
    };

    stage(0, 0);
    __syncthreads();

    int bb = 0;
    for (int c = 0; c < nch; ++c) {
        if (c + 1 < nch) stage(bb ^ 1, c + 1);

        const char* Ahs = smem + bb * GS_BUF;
        const char* Als = Ahs + GS_PLANE;
        const char* Bhs = Ahs + 2 * GS_PLANE;
        const char* Bls = Ahs + 3 * GS_PLANE;

#pragma unroll
        for (int ks = 0; ks < 2; ++ks) {
            uint32_t ah[4][4], al[4][4];
#pragma unroll
            for (int mi = 0; mi < 4; ++mi) {
                uint32_t r0 = (wm * 64 + mi * 16 + g) * GS_STRIDE + ks * 32 + tg * 4;
                ah[mi][0] = *reinterpret_cast<const uint32_t*>(Ahs + r0);
                ah[mi][1] = *reinterpret_cast<const uint32_t*>(Ahs + r0 + 8 * GS_STRIDE);
                ah[mi][2] = *reinterpret_cast<const uint32_t*>(Ahs + r0 + 16);
                ah[mi][3] = *reinterpret_cast<const uint32_t*>(Ahs + r0 + 8 * GS_STRIDE + 16);
                al[mi][0] = *reinterpret_cast<const uint32_t*>(Als + r0);
                al[mi][1] = *reinterpret_cast<const uint32_t*>(Als + r0 + 8 * GS_STRIDE);
                al[mi][2] = *reinterpret_cast<const uint32_t*>(Als + r0 + 16);
                al[mi][3] = *reinterpret_cast<const uint32_t*>(Als + r0 + 8 * GS_STRIDE + 16);
            }
#pragma unroll
            for (int ni = 0; ni < 8; ++ni) {
                uint32_t n0 = (wn * 64 + ni * 8 + g) * GS_STRIDE + ks * 32 + tg * 4;
                uint32_t bh[2], bl[2];
                bh[0] = *reinterpret_cast<const uint32_t*>(Bhs + n0);
                bh[1] = *reinterpret_cast<const uint32_t*>(Bhs + n0 + 16);
                bl[0] = *reinterpret_cast<const uint32_t*>(Bls + n0);
                bl[1] = *reinterpret_cast<const uint32_t*>(Bls + n0 + 16);
#pragma unroll
                for (int mi = 0; mi < 4; ++mi) {
                    mma_bf16(acc[mi][ni], ah[mi], bh);
                    mma_bf16(acc[mi][ni], al[mi], bh);
                    mma_bf16(acc[mi][ni], ah[mi], bl);
                }
            }
        }
        __syncthreads();
        bb ^= 1;
    }

    // epilogue: f32 stores + fused attention dot partials (per-head = per block-x)
#pragma unroll
    for (int mi = 0; mi < 4; ++mi) {
        int r0 = by * 128 + wm * 64 + mi * 16 + g;
        float ps_a = 0.f, pd_a = 0.f, ps_b = 0.f, pd_b = 0.f;
#pragma unroll
        for (int ni = 0; ni < 8; ++ni) {
            int cc = bx * 128 + wn * 64 + ni * 8 + tg * 2;
            float b0 = bias ? bias[cc]     : 0.f;
            float b1 = bias ? bias[cc + 1] : 0.f;
            float v0 = acc[mi][ni][0] + b0, v1 = acc[mi][ni][1] + b1;
            float v2 = acc[mi][ni][2] + b0, v3 = acc[mi][ni][3] + b1;
            if (r0 < M)
                *reinterpret_cast<float2*>(C + (size_t)r0 * Nn + cc) = make_float2(v0, v1);
            if (r0 + 8 < M)
                *reinterpret_cast<float2*>(C + (size_t)(r0 + 8) * Nn + cc) = make_float2(v2, v3);
            if (es) {
                float s0 = att_s[cc], s1 = att_s[cc + 1];
                float d0 = att_d[cc], d1 = att_d[cc + 1];
                ps_a += v0 * s0 + v1 * s1;
                pd_a += v0 * d0 + v1 * d1;
                ps_b += v2 * s0 + v3 * s1;
                pd_b += v2 * d0 + v3 * d1;
            }
        }
        if (es) {
#pragma unroll
            for (int o = 1; o <= 2; o <<= 1) {
                ps_a += __shfl_xor_sync(0xffffffffu, ps_a, o);
                pd_a += __shfl_xor_sync(0xffffffffu, pd_a, o);
                ps_b += __shfl_xor_sync(0xffffffffu, ps_b, o);
                pd_b += __shfl_xor_sync(0xffffffffu, pd_b, o);
            }
            if (tg == 0) {
                if (r0 < M) {
                    atomicAdd(&es[(size_t)r0 * es_stride + bx], ps_a);
                    atomicAdd(&ed[(size_t)r0 * es_stride + bx], pd_a);
                }
                if (r0 + 8 < M) {
                    atomicAdd(&es[(size_t)(r0 + 8) * es_stride + bx], ps_b);
                    atomicAdd(&ed[(size_t)(r0 + 8) * es_stride + bx], pd_b);
                }
            }
        }
    }
}

// ---------------- fused softmax + aggregate, layer 1 (edge loop unrolled x2) ----
__global__ __launch_bounds__(256)
void k_agg1(const float* __restrict__ b1) {
    int warp = (blockIdx.x * blockDim.x + threadIdx.x) >> 5;
    int lane = threadIdx.x & 31;
    if (warp >= NN) return;
    const int beg = g_rowptr[warp];
    const int end = g_rowptr[warp + 1];
    float edv[H1];
#pragma unroll
    for (int h = 0; h < H1; ++h) edv[h] = g_ed1[warp * H1 + h];

    float mx[H1] = {-1e30f, -1e30f, -1e30f, -1e30f};
    for (int p = beg + lane; p < end; p += 32) {
        int s = g_ssrc[p];
        float4 esv = *reinterpret_cast<const float4*>(g_es1 + s * 4);
        float ev[H1] = {esv.x, esv.y, esv.z, esv.w};
#pragma unroll
        for (int h = 0; h < H1; ++h) {
            float e = ev[h] + edv[h];
            e = (e >= 0.f) ? e : NEG * e;
            mx[h] = fmaxf(mx[h], e);
        }
    }
#pragma unroll
    for (int h = 0; h < H1; ++h)
#pragma unroll
        for (int off = 16; off > 0; off >>= 1)
            mx[h] = fmaxf(mx[h], __shfl_xor_sync(0xffffffffu, mx[h], off));

    float accv[16];
#pragma unroll
    for (int k = 0; k < 16; ++k) accv[k] = 0.f;
    float sm[H1] = {0.f, 0.f, 0.f, 0.f};
    int p = beg;
    for (; p + 2 <= end; p += 2) {
        int s0 = g_ssrc[p];
        int s1 = g_ssrc[p + 1];
        float4 e0v = *reinterpret_cast<const float4*>(g_es1 + s0 * 4);
        float4 e1v = *reinterpret_cast<const float4*>(g_es1 + s1 * 4);
        float ev0[H1] = {e0v.x, e0v.y, e0v.z, e0v.w};
        float ev1[H1] = {e1v.x, e1v.y, e1v.z, e1v.w};
        float ex0[H1], ex1[H1];
#pragma unroll
        for (int h = 0; h < H1; ++h) {
            float a = ev0[h] + edv[h];
            a = (a >= 0.f) ? a : NEG * a;
            ex0[h] = __expf(a - mx[h]);
            float b = ev1[h] + edv[h];
            b = (b >= 0.f) ? b : NEG * b;
            ex1[h] = __expf(b - mx[h]);
            sm[h] += ex0[h] + ex1[h];
        }
        const float* r0 = g_h1pre + (size_t)s0 * HC1;
        const float* r1 = g_h1pre + (size_t)s1 * HC1;
#pragma unroll
        for (int k = 0; k < 16; ++k) {
            int c = lane + 32 * k;
            int h = k >> 2;
            accv[k] += r0[c] * ex0[h] + r1[c] * ex1[h];
        }
    }
    if (p < end) {
        int s = g_ssrc[p];
        float4 esv = *reinterpret_cast<const float4*>(g_es1 + s * 4);
        float ev[H1] = {esv.x, esv.y, esv.z, esv.w};
        float ex[H1];
#pragma unroll
        for (int h = 0; h < H1; ++h) {
            float e = ev[h] + edv[h];
            e = (e >= 0.f) ? e : NEG * e;
            ex[h] = __expf(e - mx[h]);
            sm[h] += ex[h];
        }
        const float* row = g_h1pre + (size_t)s * HC1;
#pragma unroll
        for (int k = 0; k < 16; ++k)
            accv[k] += row[lane + 32 * k] * ex[k >> 2];
    }
#pragma unroll
    for (int k = 0; k < 16; ++k) {
        int c = lane + 32 * k;
        int h = k >> 2;
        float v = accv[k] / (sm[h] + 1e-16f) + b1[c];
        v = (v > 0.f) ? v : expm1f(v);   // ELU
        g_h1out[(size_t)warp * HC1 + c] = v;
    }
}

// ---------------- fused softmax + aggregate, layer 2 (edge loop unrolled x2) ----
__global__ __launch_bounds__(256)
void k_agg2(const float* __restrict__ b2, float* __restrict__ out) {
    int warp = (blockIdx.x * blockDim.x + threadIdx.x) >> 5;
    int lane = threadIdx.x & 31;
    if (warp >= NN) return;
    const int beg = g_rowptr[warp];
    const int end = g_rowptr[warp + 1];
    const float edv = g_ed2[warp];

    float mx = -1e30f;
    for (int p = beg + lane; p < end; p += 32) {
        float e = g_es2[g_ssrc[p]] + edv;
        e = (e >= 0.f) ? e : NEG * e;
        mx = fmaxf(mx, e);
    }
#pragma unroll
    for (int off = 16; off > 0; off >>= 1)
        mx = fmaxf(mx, __shfl_xor_sync(0xffffffffu, mx, off));

    float accv[4] = {0.f, 0.f, 0.f, 0.f};
    float sm = 0.f;
    int p = beg;
    for (; p + 2 <= end; p += 2) {
        int s0 = g_ssrc[p];
        int s1 = g_ssrc[p + 1];
        float a = g_es2[s0] + edv;
        a = (a >= 0.f) ? a : NEG * a;
        float b = g_es2[s1] + edv;
        b = (b >= 0.f) ? b : NEG * b;
        float ex0 = __expf(a - mx);
        float ex1 = __expf(b - mx);
        sm += ex0 + ex1;
        const float* r0 = g_h2pre + (size_t)s0 * FOUT;
        const float* r1 = g_h2pre + (size_t)s1 * FOUT;
#pragma unroll
        for (int k = 0; k < 4; ++k) {
            int c = lane + 32 * k;
            accv[k] += r0[c] * ex0 + r1[c] * ex1;
        }
    }
    if (p < end) {
        int s = g_ssrc[p];
        float e = g_es2[s] + edv;
        e = (e >= 0.f) ? e : NEG * e;
        float ex = __expf(e - mx);
        sm += ex;
        const float* row = g_h2pre + (size_t)s * FOUT;
#pragma unroll
        for (int k = 0; k < 4; ++k)
            accv[k] += row[lane + 32 * k] * ex;
    }
    float* outrow = out + (size_t)warp * FOUT;
    float inv = 1.f / (sm + 1e-16f);
#pragma unroll
    for (int k = 0; k < 4; ++k) {
        int c = lane + 32 * k;
        outrow[c] = accv[k] * inv + b2[c];
    }
}

// ---------------- host launcher ----------------
extern "C" void kernel_launch(void* const* d_in, const int* in_sizes, int n_in,
                              void* d_out, int out_size) {
    const float* x    = (const float*)d_in[0];
    const int*   ei   = (const int*)d_in[1];
    const float* sent = (const float*)d_in[2];
    const float* W1   = (const float*)d_in[3];
    const float* a1s  = (const float*)d_in[4];
    const float* a1d  = (const float*)d_in[5];
    const float* b1   = (const float*)d_in[6];
    const float* W2   = (const float*)d_in[7];
    const float* a2s  = (const float*)d_in[8];
    const float* a2d  = (const float*)d_in[9];
    const float* b2   = (const float*)d_in[10];
    float* out = (float*)d_out;

    static cudaStream_t s1 = nullptr;
    static cudaEvent_t  evFork = nullptr, evJoin = nullptr;
    if (!s1) {
        cudaStreamCreateWithFlags(&s1, cudaStreamNonBlocking);
        cudaEventCreateWithFlags(&evFork, cudaEventDisableTiming);
        cudaEventCreateWithFlags(&evJoin, cudaEventDisableTiming);
        cudaFuncSetAttribute(k_gemm_f32a, cudaFuncAttributeMaxDynamicSharedMemorySize, GS_SMEM);
    }

    float* h1pre; cudaGetSymbolAddress((void**)&h1pre, g_h1pre);
    float* h1out; cudaGetSymbolAddress((void**)&h1out, g_h1out);
    float* h2pre; cudaGetSymbolAddress((void**)&h2pre, g_h2pre);
    float* c1;    cudaGetSymbolAddress((void**)&c1,    g_c1);
    float* es1;   cudaGetSymbolAddress((void**)&es1,   g_es1);
    float* ed1;   cudaGetSymbolAddress((void**)&ed1,   g_ed1);
    float* es2;   cudaGetSymbolAddress((void**)&es2,   g_es2);
    float* ed2;   cudaGetSymbolAddress((void**)&ed2,   g_ed2);
    __nv_bfloat16 *w1thi, *w1tlo, *w2thi, *w2tlo;
    cudaGetSymbolAddress((void**)&w1thi, g_w1thi);
    cudaGetSymbolAddress((void**)&w1tlo, g_w1tlo);
    cudaGetSymbolAddress((void**)&w2thi, g_w2thi);
    cudaGetSymbolAddress((void**)&w2tlo, g_w2tlo);

    // zero (feeds both branches)
    k_zero<<<(NN * H1 + 255) / 256, 256>>>();
    cudaEventRecord(evFork, 0);

    // ---- side branch (stream s1): CSR build + tsplit2 (independent of GEMM1) ----
    cudaStreamWaitEvent(s1, evFork, 0);
    k_hist<<<(EE + 255) / 256, 256, 0, s1>>>(ei);
    k_scan<<<1, 1024, 0, s1>>>();
    k_scatter<<<(EE + 255) / 256, 256, 0, s1>>>(ei);
    {
        dim3 blk(32, 8);
        dim3 g2(HC1 / 32, FOUT / 32);
        k_tsplit<<<g2, blk, 0, s1>>>(W2, w2thi, w2tlo, HC1, FOUT);
    }
    cudaEventRecord(evJoin, s1);

    // ---- main branch (stream 0): c1, tsplit1, GEMM1 ----
    k_c1<<<SED / 16, 256>>>(sent, W1);
    {
        dim3 blk(32, 8);
        dim3 g1(SED / 32, HC1 / 32);
        k_tsplit<<<g1, blk>>>(W1, w1thi, w1tlo, SED, HC1);   // W1 rows 0..767
    }
    {
        dim3 grid(HC1 / 128, (NN + 127) / 128);
        k_gemm_f32a<<<grid, 128, GS_SMEM>>>(x, w1thi, w1tlo, c1, h1pre,
                                            a1s, a1d, es1, ed1, H1, NN, HC1, SED);
    }

    // join: agg1 needs CSR (side branch) + GEMM1 (main branch)
    cudaStreamWaitEvent(0, evJoin, 0);

    k_agg1<<<(NN * 32 + 255) / 256, 256>>>(b1);

    // GEMM2: h2pre = h1out @ W2, fused es2/ed2 dots  (M=20000, N=128, K=512)
    {
        dim3 grid(FOUT / 128, (NN + 127) / 128);
        k_gemm_f32a<<<grid, 128, GS_SMEM>>>(h1out, w2thi, w2tlo, (const float*)nullptr, h2pre,
                                            a2s, a2d, es2, ed2, 1, NN, FOUT, HC1);
    }

    k_agg2<<<(NN * 32 + 255) / 256, 256>>>(b2, out);
}